// round 1
// baseline (speedup 1.0000x reference)
#include <cuda_runtime.h>

#define N_VARS    100000
#define N_CLAUSES 400000
#define NNZ       1200000
#define D         128
#define EPSILON   1e-6f

// ---------------- scratch (static device globals; no runtime allocation) ----
__device__ float g_clauses[(size_t)N_CLAUSES * D];  // 204.8 MB
__device__ float g_cdeg[N_CLAUSES];                 // clause degree column
__device__ float g_acc[(size_t)N_VARS * D];         // 51.2 MB
__device__ float g_vdeg[N_VARS];                    // variable degree column

__device__ __forceinline__ void red_add_v4(float* p, float4 v) {
    asm volatile("red.global.add.v4.f32 [%0], {%1,%2,%3,%4};"
                 :: "l"(p), "f"(v.x), "f"(v.y), "f"(v.z), "f"(v.w)
                 : "memory");
}

// ---------------- zero scratch ---------------------------------------------
__global__ void k_zero() {
    size_t tid    = (size_t)blockIdx.x * blockDim.x + threadIdx.x;
    size_t stride = (size_t)gridDim.x * blockDim.x;
    float4 z = make_float4(0.f, 0.f, 0.f, 0.f);
    const size_t n1 = (size_t)N_CLAUSES * D / 4;
    for (size_t i = tid; i < n1; i += stride) reinterpret_cast<float4*>(g_clauses)[i] = z;
    const size_t n2 = N_CLAUSES / 4;
    for (size_t i = tid; i < n2; i += stride) reinterpret_cast<float4*>(g_cdeg)[i] = z;
    const size_t n3 = (size_t)N_VARS * D / 4;
    for (size_t i = tid; i < n3; i += stride) reinterpret_cast<float4*>(g_acc)[i] = z;
    const size_t n4 = N_VARS / 4;
    for (size_t i = tid; i < n4; i += stride) reinterpret_cast<float4*>(g_vdeg)[i] = z;
}

// ---------------- phase 1: scatter literals into clauses --------------------
// One warp per edge: lane L handles features [4L, 4L+4).
__global__ void k_phase1(const float* __restrict__ vars,
                         const float* __restrict__ vals,
                         const int*   __restrict__ rows,
                         const int*   __restrict__ cols) {
    int w = (blockIdx.x * blockDim.x + threadIdx.x) >> 5;
    if (w >= NNZ) return;
    int lane = threadIdx.x & 31;
    int col  = __ldg(cols + w);
    int row  = __ldg(rows + w);
    float va = __ldg(vals + w);
    int v = (col >= N_VARS) ? (col - N_VARS) : col;

    float4 s = *reinterpret_cast<const float4*>(vars + (size_t)v * D + lane * 4);
    float4 m = make_float4(s.x * va, s.y * va, s.z * va, s.w * va);
    red_add_v4(g_clauses + (size_t)row * D + lane * 4, m);
    if (lane == 0) atomicAdd(g_cdeg + row, va);
}

// ---------------- phase 2: scatter clauses back into variable acc -----------
__global__ void k_phase2(const float* __restrict__ vals,
                         const int*   __restrict__ rows,
                         const int*   __restrict__ cols) {
    int w = (blockIdx.x * blockDim.x + threadIdx.x) >> 5;
    if (w >= NNZ) return;
    int lane = threadIdx.x & 31;
    int col  = __ldg(cols + w);
    int row  = __ldg(rows + w);
    float va = __ldg(vals + w);
    int v = (col >= N_VARS) ? (col - N_VARS) : col;

    float4 c = *reinterpret_cast<const float4*>(g_clauses + (size_t)row * D + lane * 4);
    float4 m = make_float4(c.x * va, c.y * va, c.z * va, c.w * va);
    red_add_v4(g_acc + (size_t)v * D + lane * 4, m);
    if (lane == 0) atomicAdd(g_vdeg + v, __ldg(g_cdeg + row) * va);
}

// ---------------- phase 3: normalize ----------------------------------------
// One warp per variable row.
__global__ void k_phase3(const float* __restrict__ vars, float* __restrict__ out) {
    int w = (blockIdx.x * blockDim.x + threadIdx.x) >> 5;
    if (w >= N_VARS) return;
    int lane = threadIdx.x & 31;

    float deg = g_vdeg[w];
    float inv = 1.0f / fmaxf(deg, 2.0f);
    size_t off = (size_t)w * D + lane * 4;

    float4 a = *reinterpret_cast<const float4*>(g_acc + off);
    float4 x = *reinterpret_cast<const float4*>(vars + off);
    float4 vv = make_float4(x.x - a.x * inv, x.y - a.y * inv,
                            x.z - a.z * inv, x.w - a.w * inv);
    float ss = vv.x * vv.x + vv.y * vv.y + vv.z * vv.z + vv.w * vv.w;
    #pragma unroll
    for (int o = 16; o; o >>= 1) ss += __shfl_xor_sync(0xffffffffu, ss, o);
    float scale = rsqrtf(ss * (1.0f / 128.0f) + EPSILON);
    float4 o4 = make_float4(vv.x * scale, vv.y * scale, vv.z * scale, vv.w * scale);
    *reinterpret_cast<float4*>(out + off) = o4;
}

// ---------------- launcher ---------------------------------------------------
extern "C" void kernel_launch(void* const* d_in, const int* in_sizes, int n_in,
                              void* d_out, int out_size) {
    const float* vars = (const float*)d_in[0];
    const float* vals = (const float*)d_in[1];
    const int*   rows = (const int*)d_in[2];
    const int*   cols = (const int*)d_in[3];
    float* out = (float*)d_out;

    k_zero<<<4096, 256>>>();

    int edge_blocks = (NNZ * 32 + 255) / 256;       // warp per edge
    k_phase1<<<edge_blocks, 256>>>(vars, vals, rows, cols);
    k_phase2<<<edge_blocks, 256>>>(vals, rows, cols);

    int var_blocks = (N_VARS * 32 + 255) / 256;     // warp per variable
    k_phase3<<<var_blocks, 256>>>(vars, out);
}

// round 2
// speedup vs baseline: 2.2428x; 2.2428x over previous
#include <cuda_runtime.h>

#define N_VARS    100000
#define N_CLAUSES 400000
#define NNZ       1200000
#define D         128
#define EPSILON   1e-6f
#define CAP       32          // per-clause smem edge cache (avg degree ~3)

// ---------------- scratch (static device globals) ---------------------------
struct __align__(16) EdgeRec { int next; int col; float val; int pad; };

__device__ float   g_acc[(size_t)N_VARS * D];   // 51.2 MB
__device__ float   g_vdeg[N_VARS];
__device__ int     g_head[N_CLAUSES];
__device__ EdgeRec g_rec[NNZ];                  // 19.2 MB

__device__ __forceinline__ void red_add_v4(float* p, float4 v) {
    asm volatile("red.global.add.v4.f32 [%0], {%1,%2,%3,%4};"
                 :: "l"(p), "f"(v.x), "f"(v.y), "f"(v.z), "f"(v.w)
                 : "memory");
}
__device__ __forceinline__ void red_add_f(float* p, float v) {
    asm volatile("red.global.add.f32 [%0], %1;" :: "l"(p), "f"(v) : "memory");
}

// ---------------- init: zero acc/vdeg, head = -1 -----------------------------
__global__ void k_init() {
    size_t tid    = (size_t)blockIdx.x * blockDim.x + threadIdx.x;
    size_t stride = (size_t)gridDim.x * blockDim.x;
    float4 z = make_float4(0.f, 0.f, 0.f, 0.f);
    const size_t n1 = (size_t)N_VARS * D / 4;
    for (size_t i = tid; i < n1; i += stride) reinterpret_cast<float4*>(g_acc)[i] = z;
    for (size_t i = tid; i < N_VARS; i += stride) g_vdeg[i] = 0.f;
    for (size_t i = tid; i < N_CLAUSES; i += stride) g_head[i] = -1;
}

// ---------------- build per-clause linked lists ------------------------------
__global__ void k_build(const int* __restrict__ rows,
                        const int* __restrict__ cols,
                        const float* __restrict__ vals) {
    int e = blockIdx.x * blockDim.x + threadIdx.x;
    if (e >= NNZ) return;
    int r = __ldg(rows + e);
    int prev = atomicExch(&g_head[r], e);
    int col = __ldg(cols + e);
    float v = __ldg(vals + e);
    int4 rec = make_int4(prev, col, __float_as_int(v), 0);
    *reinterpret_cast<int4*>(&g_rec[e]) = rec;
}

// ---------------- fused AᵀA pass: one warp per clause ------------------------
// Walk the clause's edge list: gather var rows into a register sum, then
// RED-scatter sum*val back to each incident variable. No clause array at all.
__global__ void k_fused(const float* __restrict__ vars) {
    int w = (blockIdx.x * blockDim.x + threadIdx.x) >> 5;
    if (w >= N_CLAUSES) return;
    int lane  = threadIdx.x & 31;
    int wslot = (threadIdx.x >> 5);
    __shared__ uint2 list[8][CAP];   // (v, val) per cached edge

    int e = g_head[w];
    if (e < 0) return;

    float4 sum = make_float4(0.f, 0.f, 0.f, 0.f);
    float  deg = 0.f;
    int cnt = 0;
    int e_rest = -1;

    while (e >= 0) {
        int4 r = *reinterpret_cast<const int4*>(&g_rec[e]);  // uniform addr, bcast
        int   col = r.y;
        float val = __int_as_float(r.z);
        int v = (col >= N_VARS) ? (col - N_VARS) : col;

        float4 s = *reinterpret_cast<const float4*>(vars + (size_t)v * D + lane * 4);
        sum.x += s.x * val; sum.y += s.y * val;
        sum.z += s.z * val; sum.w += s.w * val;
        deg   += val;

        if (cnt < CAP) {
            if (lane == 0) list[wslot][cnt] = make_uint2((unsigned)v, __float_as_uint(val));
            cnt++;
        } else if (e_rest < 0) {
            e_rest = e;   // overflow tail handled below (practically never)
        }
        e = r.x;
    }
    __syncwarp();

    for (int i = 0; i < cnt; i++) {
        uint2 u = list[wslot][i];
        int   v   = (int)u.x;
        float val = __uint_as_float(u.y);
        float4 m = make_float4(sum.x * val, sum.y * val, sum.z * val, sum.w * val);
        red_add_v4(g_acc + (size_t)v * D + lane * 4, m);
        if (lane == 0) red_add_f(&g_vdeg[v], deg * val);
    }

    while (e_rest >= 0) {   // overflow tail (clauses with >CAP edges)
        int4 r = *reinterpret_cast<const int4*>(&g_rec[e_rest]);
        int   col = r.y;
        float val = __int_as_float(r.z);
        int v = (col >= N_VARS) ? (col - N_VARS) : col;
        float4 m = make_float4(sum.x * val, sum.y * val, sum.z * val, sum.w * val);
        red_add_v4(g_acc + (size_t)v * D + lane * 4, m);
        if (lane == 0) red_add_f(&g_vdeg[v], deg * val);
        e_rest = r.x;
    }
}

// ---------------- normalize: one warp per variable ---------------------------
__global__ void k_norm(const float* __restrict__ vars, float* __restrict__ out) {
    int w = (blockIdx.x * blockDim.x + threadIdx.x) >> 5;
    if (w >= N_VARS) return;
    int lane = threadIdx.x & 31;

    float deg = g_vdeg[w];
    float inv = 1.0f / fmaxf(deg, 2.0f);
    size_t off = (size_t)w * D + lane * 4;

    float4 a = *reinterpret_cast<const float4*>(g_acc + off);
    float4 x = *reinterpret_cast<const float4*>(vars + off);
    float4 vv = make_float4(x.x - a.x * inv, x.y - a.y * inv,
                            x.z - a.z * inv, x.w - a.w * inv);
    float ss = vv.x * vv.x + vv.y * vv.y + vv.z * vv.z + vv.w * vv.w;
    #pragma unroll
    for (int o = 16; o; o >>= 1) ss += __shfl_xor_sync(0xffffffffu, ss, o);
    float scale = rsqrtf(ss * (1.0f / 128.0f) + EPSILON);
    *reinterpret_cast<float4*>(out + off) =
        make_float4(vv.x * scale, vv.y * scale, vv.z * scale, vv.w * scale);
}

// ---------------- launcher ---------------------------------------------------
extern "C" void kernel_launch(void* const* d_in, const int* in_sizes, int n_in,
                              void* d_out, int out_size) {
    const float* vars = (const float*)d_in[0];
    const float* vals = (const float*)d_in[1];
    const int*   rows = (const int*)d_in[2];
    const int*   cols = (const int*)d_in[3];
    float* out = (float*)d_out;

    k_init<<<4096, 256>>>();
    k_build<<<(NNZ + 255) / 256, 256>>>(rows, cols, vals);
    k_fused<<<(N_CLAUSES * 32 + 255) / 256, 256>>>(vars);
    k_norm<<<(N_VARS * 32 + 255) / 256, 256>>>(vars, out);
}